// round 1
// baseline (speedup 1.0000x reference)
#include <cuda_runtime.h>
#include <math_constants.h>

#define SB   2
#define SS   2048
#define SD   512
#define SH   8
#define SHD  64
#define KTOP 307
#define RC   16
#define HWIN 16
#define MROWS (SB*SS)   // 4096

// ---------------- scratch (device globals; no allocation allowed) ----------------
__device__ float g_Q  [(size_t)SB*SS*SD];
__device__ float g_K  [(size_t)SB*SS*SD];
__device__ float g_V  [(size_t)SB*SS*SD];
__device__ float g_H1 [(size_t)SB*SS*(SD/2)];
__device__ float g_IMP[SB*SS];
__device__ int   g_FLAG[SB*SS];
__device__ int   g_LIST[SB*KTOP];
__device__ float g_ATT[(size_t)SB*SS*SD];

// ---------------- tiled fp32 GEMM: C = A[M,K] @ W[K,N] + bias, optional ReLU ------
// BM=64, BN=64, BK=16, 256 threads, 4x4 microtile per thread.
__global__ void gemm_bias(const float* __restrict__ A, const float* __restrict__ W,
                          const float* __restrict__ bias, float* __restrict__ C,
                          int M, int N, int K, int relu)
{
    __shared__ float As[16][65];   // [k][m], padded
    __shared__ float Bs[16][64];   // [k][n]
    const int tid = threadIdx.x;
    const int tx = tid & 15, ty = tid >> 4;
    const int m0 = blockIdx.y * 64, n0 = blockIdx.x * 64;

    float acc[4][4];
#pragma unroll
    for (int i = 0; i < 4; i++)
#pragma unroll
        for (int j = 0; j < 4; j++) acc[i][j] = 0.f;

    const int ra = tid >> 2, ca = (tid & 3) << 2;   // A tile load coords
    const int rb = tid >> 4, cb = (tid & 15) << 2;  // B tile load coords

    for (int k0 = 0; k0 < K; k0 += 16) {
        float4 av = *(const float4*)&A[(size_t)(m0 + ra) * K + k0 + ca];
        As[ca + 0][ra] = av.x; As[ca + 1][ra] = av.y;
        As[ca + 2][ra] = av.z; As[ca + 3][ra] = av.w;
        float4 bv = *(const float4*)&W[(size_t)(k0 + rb) * N + n0 + cb];
        *(float4*)&Bs[rb][cb] = bv;
        __syncthreads();
#pragma unroll
        for (int k = 0; k < 16; k++) {
            float ar[4], br[4];
#pragma unroll
            for (int i = 0; i < 4; i++) ar[i] = As[k][ty * 4 + i];
#pragma unroll
            for (int j = 0; j < 4; j++) br[j] = Bs[k][tx * 4 + j];
#pragma unroll
            for (int i = 0; i < 4; i++)
#pragma unroll
                for (int j = 0; j < 4; j++) acc[i][j] += ar[i] * br[j];
        }
        __syncthreads();
    }
#pragma unroll
    for (int i = 0; i < 4; i++) {
        int m = m0 + ty * 4 + i;
#pragma unroll
        for (int j = 0; j < 4; j++) {
            int nn = n0 + tx * 4 + j;
            float v = acc[i][j] + bias[nn];
            if (relu) v = fmaxf(v, 0.f);
            C[(size_t)m * N + nn] = v;
        }
    }
}

// ---------------- importance: sigmoid(h1 @ Ws2 + bs2), one warp per row ----------
__global__ void imp_kernel(const float* __restrict__ H1, const float* __restrict__ Ws2,
                           const float* __restrict__ bs2, float* __restrict__ IMP)
{
    int row = blockIdx.x * 8 + (threadIdx.x >> 5);
    int l   = threadIdx.x & 31;
    const float* h = H1 + (size_t)row * 256;
    float acc = 0.f;
#pragma unroll
    for (int c = l; c < 256; c += 32) acc += h[c] * Ws2[c];
#pragma unroll
    for (int o = 16; o; o >>= 1) acc += __shfl_xor_sync(0xffffffffu, acc, o);
    if (l == 0) {
        float z = acc + bs2[0];
        IMP[row] = 1.f / (1.f + __expf(-z));
    }
}

// ---------------- exact top-KTOP via rank counting + compaction ------------------
__global__ void topk_kernel(const float* __restrict__ IMP, int* __restrict__ FLAG,
                            int* __restrict__ LIST)
{
    int b = blockIdx.x;
    __shared__ float s[SS];
    __shared__ unsigned char f[SS];
    for (int i = threadIdx.x; i < SS; i += blockDim.x) s[i] = IMP[b * SS + i];
    __syncthreads();
    for (int i = threadIdx.x; i < SS; i += blockDim.x) {
        float vi = s[i];
        int cnt = 0;
        for (int j = 0; j < SS; j++) {
            float vj = s[j];
            cnt += (vj > vi) || (vj == vi && j < i);
        }
        int fl = (cnt < KTOP) ? 1 : 0;
        f[i] = (unsigned char)fl;
        FLAG[b * SS + i] = fl;
    }
    __syncthreads();
    for (int i = threadIdx.x; i < SS; i += blockDim.x) {
        if (f[i]) {
            int pos = 0;
            for (int j = 0; j < i; j++) pos += f[j];
            LIST[b * KTOP + pos] = i;
        }
    }
}

// ---------------- kernel A: non-important rows (<=33 keys), block per (b,i) ------
__global__ void attn_sparse(const float* __restrict__ Q, const float* __restrict__ K,
                            const float* __restrict__ V, const int* __restrict__ rand_idx,
                            const int* __restrict__ FLAG, float* __restrict__ ATT)
{
    int bi = blockIdx.x;            // b*SS + i
    if (FLAG[bi]) return;           // dense path handles important rows
    int b = bi >> 11, i = bi & (SS - 1);

    __shared__ float qsh[SD];
    __shared__ int   list[40];
    __shared__ int   nk_sh;
    __shared__ float p[SH][64];

    const float* qrow = Q + (size_t)bi * SD;
    for (int t = threadIdx.x; t < SD; t += 256) qsh[t] = qrow[t];

    if (threadIdx.x == 0) {
        int lo = i - HWIN; if (lo < 0) lo = 0;
        int n = 0;
        for (int j = lo; j <= i; j++) list[n++] = j;
        int nw = n;
        for (int r = 0; r < RC; r++) {
            int j = rand_idx[(size_t)bi * RC + r];
            if (j <= i && j < lo) {           // causal and not in window
                bool dup = false;
                for (int t = nw; t < n; t++) if (list[t] == j) { dup = true; break; }
                if (!dup) list[n++] = j;
            }
        }
        nk_sh = n;
    }
    __syncthreads();

    int h = threadIdx.x >> 5, l = threadIdx.x & 31;
    int n = nk_sh;
    const float* qh = qsh + h * SHD;

    float s0 = -CUDART_INF_F, s1 = -CUDART_INF_F;
    if (l < n) {
        const float* kr = K + ((size_t)b * SS + list[l]) * SD + h * SHD;
        float acc = 0.f;
#pragma unroll
        for (int d = 0; d < SHD; d += 4) {
            float4 kv = *(const float4*)(kr + d);
            acc += kv.x * qh[d] + kv.y * qh[d + 1] + kv.z * qh[d + 2] + kv.w * qh[d + 3];
        }
        s0 = acc * 0.125f;
    }
    if (l + 32 < n) {
        const float* kr = K + ((size_t)b * SS + list[l + 32]) * SD + h * SHD;
        float acc = 0.f;
#pragma unroll
        for (int d = 0; d < SHD; d += 4) {
            float4 kv = *(const float4*)(kr + d);
            acc += kv.x * qh[d] + kv.y * qh[d + 1] + kv.z * qh[d + 2] + kv.w * qh[d + 3];
        }
        s1 = acc * 0.125f;
    }
    float mx = fmaxf(s0, s1);
#pragma unroll
    for (int o = 16; o; o >>= 1) mx = fmaxf(mx, __shfl_xor_sync(0xffffffffu, mx, o));
    float e0 = (l < n)      ? __expf(s0 - mx) : 0.f;
    float e1 = (l + 32 < n) ? __expf(s1 - mx) : 0.f;
    float sum = e0 + e1;
#pragma unroll
    for (int o = 16; o; o >>= 1) sum += __shfl_xor_sync(0xffffffffu, sum, o);
    float inv = 1.f / sum;
    p[h][l] = e0;
    p[h][l + 32] = e1;
    __syncwarp();

    float a0 = 0.f, a1 = 0.f;
    for (int t = 0; t < n; t++) {
        float pj = p[h][t];
        const float* vr = V + ((size_t)b * SS + list[t]) * SD + h * SHD;
        a0 += pj * vr[l];
        a1 += pj * vr[l + 32];
    }
    float* orow = ATT + (size_t)bi * SD + h * SHD;
    orow[l]      = a0 * inv;
    orow[l + 32] = a1 * inv;
}

// ---------------- kernel B: important rows, full causal prefix -------------------
__global__ void attn_dense(const float* __restrict__ Q, const float* __restrict__ K,
                           const float* __restrict__ V, const int* __restrict__ LIST,
                           float* __restrict__ ATT)
{
    int b = blockIdx.y, h = blockIdx.z;
    int i = LIST[b * KTOP + blockIdx.x];
    int t = threadIdx.x;                       // 128 threads

    __shared__ float sc[SS];
    __shared__ float qsh[SHD];
    __shared__ float red[128];
    __shared__ float ob[128];

    const float* qr = Q + ((size_t)b * SS + i) * SD + h * SHD;
    if (t < SHD) qsh[t] = qr[t];
    __syncthreads();

    int n = i + 1;
    float lmax = -CUDART_INF_F;
    for (int j = t; j < n; j += 128) {
        const float* kr = K + ((size_t)b * SS + j) * SD + h * SHD;
        float acc = 0.f;
#pragma unroll
        for (int d = 0; d < SHD; d += 4) {
            float4 kv = *(const float4*)(kr + d);
            acc += kv.x * qsh[d] + kv.y * qsh[d + 1] + kv.z * qsh[d + 2] + kv.w * qsh[d + 3];
        }
        float s = acc * 0.125f;
        sc[j] = s;
        lmax = fmaxf(lmax, s);
    }
    red[t] = lmax;
    __syncthreads();
#pragma unroll
    for (int o = 64; o; o >>= 1) {
        if (t < o) red[t] = fmaxf(red[t], red[t + o]);
        __syncthreads();
    }
    float mx = red[0];
    __syncthreads();

    float lsum = 0.f;
    for (int j = t; j < n; j += 128) {
        float e = __expf(sc[j] - mx);
        sc[j] = e;
        lsum += e;
    }
    red[t] = lsum;
    __syncthreads();
#pragma unroll
    for (int o = 64; o; o >>= 1) {
        if (t < o) red[t] += red[t + o];
        __syncthreads();
    }
    float inv = 1.f / red[0];
    __syncthreads();

    int d = t & 63, part = t >> 6;
    float acc = 0.f;
    for (int j = part; j < n; j += 2)
        acc += sc[j] * V[((size_t)b * SS + j) * SD + h * SHD + d];
    ob[t] = acc;
    __syncthreads();
    if (part == 0)
        ATT[((size_t)b * SS + i) * SD + h * SHD + d] = (acc + ob[t + 64]) * inv;
}

// ---------------- launch ---------------------------------------------------------
extern "C" void kernel_launch(void* const* d_in, const int* in_sizes, int n_in,
                              void* d_out, int out_size)
{
    const float* x    = (const float*)d_in[0];
    const float* Wq   = (const float*)d_in[1];
    const float* bq   = (const float*)d_in[2];
    const float* Wk   = (const float*)d_in[3];
    const float* bk   = (const float*)d_in[4];
    const float* Wv   = (const float*)d_in[5];
    const float* bv   = (const float*)d_in[6];
    const float* Wo   = (const float*)d_in[7];
    const float* bo   = (const float*)d_in[8];
    const float* Ws1  = (const float*)d_in[9];
    const float* bs1  = (const float*)d_in[10];
    const float* Ws2  = (const float*)d_in[11];
    const float* bs2  = (const float*)d_in[12];
    const int*   ridx = (const int*)  d_in[13];
    float* out = (float*)d_out;

    float *Q, *K, *V, *H1, *IMP, *ATT;
    int *FLAG, *LIST;
    cudaGetSymbolAddress((void**)&Q,   g_Q);
    cudaGetSymbolAddress((void**)&K,   g_K);
    cudaGetSymbolAddress((void**)&V,   g_V);
    cudaGetSymbolAddress((void**)&H1,  g_H1);
    cudaGetSymbolAddress((void**)&IMP, g_IMP);
    cudaGetSymbolAddress((void**)&ATT, g_ATT);
    cudaGetSymbolAddress((void**)&FLAG, g_FLAG);
    cudaGetSymbolAddress((void**)&LIST, g_LIST);

    dim3 gQKV(SD / 64, MROWS / 64);      // (8, 64)
    dim3 gS1 ((SD / 2) / 64, MROWS / 64);// (4, 64)

    gemm_bias<<<gQKV, 256>>>(x, Wq, bq, Q, MROWS, SD, SD, 0);
    gemm_bias<<<gQKV, 256>>>(x, Wk, bk, K, MROWS, SD, SD, 0);
    gemm_bias<<<gQKV, 256>>>(x, Wv, bv, V, MROWS, SD, SD, 0);
    gemm_bias<<<gS1,  256>>>(x, Ws1, bs1, H1, MROWS, SD / 2, SD, 1);

    imp_kernel<<<MROWS / 8, 256>>>(H1, Ws2, bs2, IMP);
    topk_kernel<<<SB, 512>>>(IMP, FLAG, LIST);

    attn_sparse<<<MROWS, 256>>>(Q, K, V, ridx, FLAG, ATT);
    attn_dense<<<dim3(KTOP, SB, SH), 128>>>(Q, K, V, LIST, ATT);

    gemm_bias<<<gQKV, 256>>>(ATT, Wo, bo, out, MROWS, SD, SD, 0);
}

// round 2
// speedup vs baseline: 1.3196x; 1.3196x over previous
#include <cuda_runtime.h>
#include <math_constants.h>

#define SB   2
#define SS   2048
#define SD   512
#define SH   8
#define SHD  64
#define KTOP 307
#define RC   16
#define HWIN 16
#define MROWS (SB*SS)           // 4096
#define QT   ((KTOP + 31) / 32) // 10 query tiles per (b,h)

// ---------------- scratch (device globals; no allocation allowed) ----------------
__device__ float g_Q  [(size_t)SB*SS*SD];
__device__ float g_K  [(size_t)SB*SS*SD];
__device__ float g_V  [(size_t)SB*SS*SD];
__device__ float g_H1 [(size_t)SB*SS*(SD/2)];
__device__ float g_IMP[SB*SS];
__device__ int   g_FLAG[SB*SS];
__device__ int   g_LIST[SB*KTOP];
__device__ float g_ATT[(size_t)SB*SS*SD];

// ================= GEMM core: 64x64 tile, BK=16, 256 thr, 4x4 micro ==============
struct GSmem { float As[16][68]; float Bs[16][68]; };

__device__ __forceinline__ void gemm_body(GSmem& sm,
    const float* __restrict__ A, const float* __restrict__ W,
    const float* __restrict__ bias, float* __restrict__ C,
    int N, int K, int relu, int m0, int n0)
{
    const int tid = threadIdx.x;
    const int tx = tid & 15, ty = tid >> 4;
    const int ra = tid >> 2, ca = (tid & 3) << 2;   // A: 64 rows x 16 k
    const int rb = tid >> 4, cb = (tid & 15) << 2;  // W: 16 k x 64 n

    float acc[4][4];
#pragma unroll
    for (int i = 0; i < 4; i++)
#pragma unroll
        for (int j = 0; j < 4; j++) acc[i][j] = 0.f;

    const float* Ap = A + (size_t)(m0 + ra) * K + ca;
    const float* Wp = W + (size_t)rb * N + n0 + cb;

    float4 av = *(const float4*)Ap;
    float4 bv = *(const float4*)Wp;

#pragma unroll 1
    for (int k0 = 0; k0 < K; k0 += 16) {
        sm.As[ca + 0][ra] = av.x; sm.As[ca + 1][ra] = av.y;
        sm.As[ca + 2][ra] = av.z; sm.As[ca + 3][ra] = av.w;
        *(float4*)&sm.Bs[rb][cb] = bv;
        __syncthreads();

        float4 av2 = av, bv2 = bv;
        if (k0 + 16 < K) {
            av2 = *(const float4*)(Ap + k0 + 16);
            bv2 = *(const float4*)(Wp + (size_t)(k0 + 16) * N);
        }
#pragma unroll
        for (int k = 0; k < 16; k++) {
            float4 a4 = *(const float4*)&sm.As[k][ty * 4];
            float4 b4 = *(const float4*)&sm.Bs[k][tx * 4];
            float ar[4] = {a4.x, a4.y, a4.z, a4.w};
            float br[4] = {b4.x, b4.y, b4.z, b4.w};
#pragma unroll
            for (int i = 0; i < 4; i++)
#pragma unroll
                for (int j = 0; j < 4; j++) acc[i][j] += ar[i] * br[j];
        }
        __syncthreads();
        av = av2; bv = bv2;
    }
#pragma unroll
    for (int i = 0; i < 4; i++) {
        int m = m0 + ty * 4 + i;
        float4 o;
        o.x = acc[i][0] + bias[n0 + tx * 4 + 0];
        o.y = acc[i][1] + bias[n0 + tx * 4 + 1];
        o.z = acc[i][2] + bias[n0 + tx * 4 + 2];
        o.w = acc[i][3] + bias[n0 + tx * 4 + 3];
        if (relu) { o.x = fmaxf(o.x, 0.f); o.y = fmaxf(o.y, 0.f);
                    o.z = fmaxf(o.z, 0.f); o.w = fmaxf(o.w, 0.f); }
        *(float4*)&C[(size_t)m * N + n0 + tx * 4] = o;
    }
}

// fused QKV + scorer-hidden GEMM: 28 column-blocks = Q|K|V|H1
__global__ void gemm_qkvh(const float* __restrict__ x,
    const float* __restrict__ Wq, const float* __restrict__ bq,
    const float* __restrict__ Wk, const float* __restrict__ bk,
    const float* __restrict__ Wv, const float* __restrict__ bv,
    const float* __restrict__ Ws1, const float* __restrict__ bs1)
{
    __shared__ GSmem sm;
    int nblk = blockIdx.x * 64;
    int m0 = blockIdx.y * 64;
    if (nblk < 512)
        gemm_body(sm, x, Wq, bq, g_Q, 512, 512, 0, m0, nblk);
    else if (nblk < 1024)
        gemm_body(sm, x, Wk, bk, g_K, 512, 512, 0, m0, nblk - 512);
    else if (nblk < 1536)
        gemm_body(sm, x, Wv, bv, g_V, 512, 512, 0, m0, nblk - 1024);
    else
        gemm_body(sm, x, Ws1, bs1, g_H1, 256, 512, 1, m0, nblk - 1536);
}

__global__ void gemm_out(const float* __restrict__ A, const float* __restrict__ W,
                         const float* __restrict__ bias, float* __restrict__ C)
{
    __shared__ GSmem sm;
    gemm_body(sm, A, W, bias, C, 512, 512, 0, blockIdx.y * 64, blockIdx.x * 64);
}

// ---------------- importance: sigmoid(h1 @ Ws2 + bs2), one warp per row ----------
__global__ void imp_kernel(const float* __restrict__ H1, const float* __restrict__ Ws2,
                           const float* __restrict__ bs2, float* __restrict__ IMP)
{
    int row = blockIdx.x * 8 + (threadIdx.x >> 5);
    int l   = threadIdx.x & 31;
    const float* h = H1 + (size_t)row * 256;
    float acc = 0.f;
#pragma unroll
    for (int c = l; c < 256; c += 32) acc += h[c] * Ws2[c];
#pragma unroll
    for (int o = 16; o; o >>= 1) acc += __shfl_xor_sync(0xffffffffu, acc, o);
    if (l == 0) {
        float z = acc + bs2[0];
        IMP[row] = 1.f / (1.f + __expf(-z));
    }
}

// ---------------- exact top-KTOP via rank counting + compaction ------------------
__global__ void topk_kernel(const float* __restrict__ IMP, int* __restrict__ FLAG,
                            int* __restrict__ LIST)
{
    int b = blockIdx.x;
    __shared__ float s[SS];
    __shared__ unsigned char f[SS];
    for (int i = threadIdx.x; i < SS; i += blockDim.x) s[i] = IMP[b * SS + i];
    __syncthreads();
    for (int i = threadIdx.x; i < SS; i += blockDim.x) {
        float vi = s[i];
        int cnt = 0;
        for (int j = 0; j < SS; j++) {
            float vj = s[j];
            cnt += (vj > vi) || (vj == vi && j < i);
        }
        int fl = (cnt < KTOP) ? 1 : 0;
        f[i] = (unsigned char)fl;
        FLAG[b * SS + i] = fl;
    }
    __syncthreads();
    for (int i = threadIdx.x; i < SS; i += blockDim.x) {
        if (f[i]) {
            int pos = 0;
            for (int j = 0; j < i; j++) pos += f[j];
            LIST[b * KTOP + pos] = i;
        }
    }
}

// ---------------- kernel A: non-important rows (<=33 keys), block per (b,i) ------
__global__ void attn_sparse(const float* __restrict__ Q, const float* __restrict__ K,
                            const float* __restrict__ V, const int* __restrict__ rand_idx,
                            const int* __restrict__ FLAG, float* __restrict__ ATT)
{
    int bi = blockIdx.x;            // b*SS + i
    if (FLAG[bi]) return;           // dense path handles important rows
    int b = bi >> 11, i = bi & (SS - 1);

    __shared__ float qsh[SD];
    __shared__ int   list[40];
    __shared__ int   nk_sh;
    __shared__ float p[SH][64];

    const float* qrow = Q + (size_t)bi * SD;
    for (int t = threadIdx.x; t < SD; t += 256) qsh[t] = qrow[t];

    if (threadIdx.x == 0) {
        int lo = i - HWIN; if (lo < 0) lo = 0;
        int n = 0;
        for (int j = lo; j <= i; j++) list[n++] = j;
        int nw = n;
        for (int r = 0; r < RC; r++) {
            int j = rand_idx[(size_t)bi * RC + r];
            if (j <= i && j < lo) {
                bool dup = false;
                for (int t = nw; t < n; t++) if (list[t] == j) { dup = true; break; }
                if (!dup) list[n++] = j;
            }
        }
        nk_sh = n;
    }
    __syncthreads();

    int h = threadIdx.x >> 5, l = threadIdx.x & 31;
    int n = nk_sh;
    const float* qh = qsh + h * SHD;

    float s0 = -CUDART_INF_F, s1 = -CUDART_INF_F;
    if (l < n) {
        const float* kr = K + ((size_t)b * SS + list[l]) * SD + h * SHD;
        float acc = 0.f;
#pragma unroll
        for (int d = 0; d < SHD; d += 4) {
            float4 kv = *(const float4*)(kr + d);
            acc += kv.x * qh[d] + kv.y * qh[d + 1] + kv.z * qh[d + 2] + kv.w * qh[d + 3];
        }
        s0 = acc * 0.125f;
    }
    if (l + 32 < n) {
        const float* kr = K + ((size_t)b * SS + list[l + 32]) * SD + h * SHD;
        float acc = 0.f;
#pragma unroll
        for (int d = 0; d < SHD; d += 4) {
            float4 kv = *(const float4*)(kr + d);
            acc += kv.x * qh[d] + kv.y * qh[d + 1] + kv.z * qh[d + 2] + kv.w * qh[d + 3];
        }
        s1 = acc * 0.125f;
    }
    float mx = fmaxf(s0, s1);
#pragma unroll
    for (int o = 16; o; o >>= 1) mx = fmaxf(mx, __shfl_xor_sync(0xffffffffu, mx, o));
    float e0 = (l < n)      ? __expf(s0 - mx) : 0.f;
    float e1 = (l + 32 < n) ? __expf(s1 - mx) : 0.f;
    float sum = e0 + e1;
#pragma unroll
    for (int o = 16; o; o >>= 1) sum += __shfl_xor_sync(0xffffffffu, sum, o);
    float inv = 1.f / sum;
    p[h][l] = e0;
    p[h][l + 32] = e1;
    __syncwarp();

    float a0 = 0.f, a1 = 0.f;
    for (int t = 0; t < n; t++) {
        float pj = p[h][t];
        const float* vr = V + ((size_t)b * SS + list[t]) * SD + h * SHD;
        a0 += pj * vr[l];
        a1 += pj * vr[l + 32];
    }
    float* orow = ATT + (size_t)bi * SD + h * SHD;
    orow[l]      = a0 * inv;
    orow[l + 32] = a1 * inv;
}

// ---------------- kernel B: flash-style q-tiled dense rows -----------------------
// block = (q-tile of 32 sorted important rows, b, h); 256 threads = 8 warps,
// warp w owns 4 queries; lane = key within 32-wide j tile.
__global__ void attn_dense(const float* __restrict__ Q, const float* __restrict__ K,
                           const float* __restrict__ V, const int* __restrict__ LIST,
                           float* __restrict__ ATT)
{
    int qt = blockIdx.x, b = blockIdx.y, h = blockIdx.z;
    __shared__ float2 Qs2[32][32];   // [q][dpair]
    __shared__ float2 Ks2[32][33];   // [dpair][j]
    __shared__ float  Vs[32][64];    // [j][d]
    __shared__ float  Ps[32][34];    // [q][j]
    __shared__ int    qi[32];

    int tid = threadIdx.x, w = tid >> 5, l = tid & 31;
    int base = qt * 32;
    int nq = KTOP - base; if (nq > 32) nq = 32;
    if (tid < 32)
        qi[tid] = (tid < nq) ? LIST[b * KTOP + base + tid] : -1;
    __syncthreads();
    int imax = qi[nq - 1];

    int row = tid >> 3, d0 = (tid & 7) * 8;
    {
        int q = qi[row]; int qs = q < 0 ? 0 : q;
        const float* src = Q + ((size_t)b * SS + qs) * SD + h * SHD + d0;
        float4 a = *(const float4*)src;
        float4 c = *(const float4*)(src + 4);
        int dp = d0 >> 1;
        Qs2[row][dp + 0] = make_float2(a.x, a.y);
        Qs2[row][dp + 1] = make_float2(a.z, a.w);
        Qs2[row][dp + 2] = make_float2(c.x, c.y);
        Qs2[row][dp + 3] = make_float2(c.z, c.w);
    }

    int qg[4];
    float m[4], lsum[4], a0[4], a1[4];
#pragma unroll
    for (int c = 0; c < 4; c++) {
        qg[c] = qi[w * 4 + c];
        m[c] = -CUDART_INF_F; lsum[c] = 0.f; a0[c] = 0.f; a1[c] = 0.f;
    }

    for (int j0 = 0; j0 <= imax; j0 += 32) {
        __syncthreads();
        {
            int j = j0 + row;
            const float* kp = K + ((size_t)b * SS + j) * SD + h * SHD + d0;
            float4 ka = *(const float4*)kp;
            float4 kb = *(const float4*)(kp + 4);
            int dp = d0 >> 1;
            Ks2[dp + 0][row] = make_float2(ka.x, ka.y);
            Ks2[dp + 1][row] = make_float2(ka.z, ka.w);
            Ks2[dp + 2][row] = make_float2(kb.x, kb.y);
            Ks2[dp + 3][row] = make_float2(kb.z, kb.w);
            const float* vp = V + ((size_t)b * SS + j) * SD + h * SHD + d0;
            *(float4*)&Vs[row][d0]     = *(const float4*)vp;
            *(float4*)&Vs[row][d0 + 4] = *(const float4*)(vp + 4);
        }
        __syncthreads();

        int jg = j0 + l;
        float s[4] = {0.f, 0.f, 0.f, 0.f};
#pragma unroll
        for (int dp = 0; dp < 32; dp++) {
            float2 kd = Ks2[dp][l];
#pragma unroll
            for (int c = 0; c < 4; c++) {
                float2 qv = Qs2[w * 4 + c][dp];
                s[c] += qv.x * kd.x + qv.y * kd.y;
            }
        }
#pragma unroll
        for (int c = 0; c < 4; c++) {
            bool ok = (jg <= qg[c]);
            float sc = ok ? s[c] * 0.125f : -CUDART_INF_F;
            float tm = sc;
#pragma unroll
            for (int o = 16; o; o >>= 1) tm = fmaxf(tm, __shfl_xor_sync(0xffffffffu, tm, o));
            float newm = fmaxf(m[c], tm);
            float p = 0.f;
            if (newm != -CUDART_INF_F) {
                p = ok ? __expf(sc - newm) : 0.f;
                float ps = p;
#pragma unroll
                for (int o = 16; o; o >>= 1) ps += __shfl_xor_sync(0xffffffffu, ps, o);
                float scale = (m[c] == -CUDART_INF_F) ? 0.f : __expf(m[c] - newm);
                lsum[c] = lsum[c] * scale + ps;
                a0[c] *= scale; a1[c] *= scale;
                m[c] = newm;
            }
            Ps[w * 4 + c][l] = p;
        }
        __syncwarp();
#pragma unroll
        for (int jp = 0; jp < 16; jp++) {
            int j = jp * 2;
            float v0a = Vs[j][l],      v1a = Vs[j + 1][l];
            float v0b = Vs[j][l + 32], v1b = Vs[j + 1][l + 32];
#pragma unroll
            for (int c = 0; c < 4; c++) {
                float2 pp = *(const float2*)&Ps[w * 4 + c][j];
                a0[c] += pp.x * v0a + pp.y * v1a;
                a1[c] += pp.x * v0b + pp.y * v1b;
            }
        }
    }

#pragma unroll
    for (int c = 0; c < 4; c++) {
        if (qg[c] >= 0) {
            float inv = 1.f / lsum[c];
            float* orow = ATT + ((size_t)b * SS + qg[c]) * SD + h * SHD;
            orow[l]      = a0[c] * inv;
            orow[l + 32] = a1[c] * inv;
        }
    }
}

// ---------------- launch ---------------------------------------------------------
extern "C" void kernel_launch(void* const* d_in, const int* in_sizes, int n_in,
                              void* d_out, int out_size)
{
    const float* x    = (const float*)d_in[0];
    const float* Wq   = (const float*)d_in[1];
    const float* bq   = (const float*)d_in[2];
    const float* Wk   = (const float*)d_in[3];
    const float* bk   = (const float*)d_in[4];
    const float* Wv   = (const float*)d_in[5];
    const float* bv   = (const float*)d_in[6];
    const float* Wo   = (const float*)d_in[7];
    const float* bo   = (const float*)d_in[8];
    const float* Ws1  = (const float*)d_in[9];
    const float* bs1  = (const float*)d_in[10];
    const float* Ws2  = (const float*)d_in[11];
    const float* bs2  = (const float*)d_in[12];
    const int*   ridx = (const int*)  d_in[13];
    float* out = (float*)d_out;

    float *Q, *K, *V, *H1, *IMP, *ATT;
    int *FLAG, *LIST;
    cudaGetSymbolAddress((void**)&Q,   g_Q);
    cudaGetSymbolAddress((void**)&K,   g_K);
    cudaGetSymbolAddress((void**)&V,   g_V);
    cudaGetSymbolAddress((void**)&H1,  g_H1);
    cudaGetSymbolAddress((void**)&IMP, g_IMP);
    cudaGetSymbolAddress((void**)&ATT, g_ATT);
    cudaGetSymbolAddress((void**)&FLAG, g_FLAG);
    cudaGetSymbolAddress((void**)&LIST, g_LIST);

    gemm_qkvh<<<dim3(28, 64), 256>>>(x, Wq, bq, Wk, bk, Wv, bv, Ws1, bs1);

    imp_kernel<<<MROWS / 8, 256>>>(H1, Ws2, bs2, IMP);
    topk_kernel<<<SB, 512>>>(IMP, FLAG, LIST);

    attn_sparse<<<MROWS, 256>>>(Q, K, V, ridx, FLAG, ATT);
    attn_dense<<<dim3(QT, SB, SH), 256>>>(Q, K, V, LIST, ATT);

    gemm_out<<<dim3(8, 64), 256>>>(ATT, Wo, bo, out);
}

// round 3
// speedup vs baseline: 1.7432x; 1.3211x over previous
#include <cuda_runtime.h>
#include <math_constants.h>

#define SB   2
#define SS   2048
#define SD   512
#define SH   8
#define SHD  64
#define KTOP 307
#define RC   16
#define HWIN 16
#define MROWS (SB*SS)           // 4096
#define QT   ((KTOP + 31) / 32) // 10 query tiles per (b,h)

typedef unsigned long long ull;

// ---------------- f32x2 helpers --------------------------------------------------
__device__ __forceinline__ void fma2(ull& acc, ull a, ull b) {
    asm("fma.rn.f32x2 %0, %1, %2, %0;" : "+l"(acc) : "l"(a), "l"(b));
}
__device__ __forceinline__ ull mul2(ull a, ull b) {
    ull r; asm("mul.rn.f32x2 %0, %1, %2;" : "=l"(r) : "l"(a), "l"(b)); return r;
}
__device__ __forceinline__ ull pack2(float x, float y) {
    ull r; asm("mov.b64 %0, {%1, %2};" : "=l"(r) : "f"(x), "f"(y)); return r;
}
__device__ __forceinline__ float2 unpack2(ull v) {
    float2 r; asm("mov.b64 {%0, %1}, %2;" : "=f"(r.x), "=f"(r.y) : "l"(v)); return r;
}

// ---------------- scratch --------------------------------------------------------
__device__ float g_Q  [(size_t)SB*SS*SD];
__device__ float g_K  [(size_t)SB*SS*SD];
__device__ float g_V  [(size_t)SB*SS*SD];
__device__ float g_H1 [(size_t)SB*SS*(SD/2)];
__device__ float g_IMP[SB*SS];
__device__ int   g_FLAG[SB*SS];
__device__ int   g_LIST[SB*KTOP];
__device__ float g_ATT[(size_t)SB*SS*SD];

// ================= GEMM: 64x128 tile, BK=16, 128 thr, 8x8 micro, f32x2 ===========
struct GS { float As[16][64]; float Bs[16][128]; };

__device__ __forceinline__ void gemm_body(GS& sm,
    const float* __restrict__ A, const float* __restrict__ W,
    const float* __restrict__ bias, float* __restrict__ C,
    int N, int K, int relu, int m0, int n0)
{
    const int tid = threadIdx.x;            // 128
    const int tx = tid & 15, ty = tid >> 4; // micro: m=ty*8, n=tx*8
    const int ra = tid >> 1, ca = (tid & 1) * 8;   // A: 64 rows x 16k
    const int rb = tid >> 5, cb = (tid & 31) * 4;  // B: 16k x 128n (rows rb+{0,4,8,12})

    ull acc[8][4];
#pragma unroll
    for (int i = 0; i < 8; i++)
#pragma unroll
        for (int p = 0; p < 4; p++) acc[i][p] = 0ull;

    const float* Ap = A + (size_t)(m0 + ra) * K + ca;
    const float* Wp = W + n0 + cb;

    float4 a0 = *(const float4*)Ap;
    float4 a1 = *(const float4*)(Ap + 4);
    float4 b0 = *(const float4*)(Wp + (size_t)(rb     ) * N);
    float4 b1 = *(const float4*)(Wp + (size_t)(rb +  4) * N);
    float4 b2 = *(const float4*)(Wp + (size_t)(rb +  8) * N);
    float4 b3 = *(const float4*)(Wp + (size_t)(rb + 12) * N);

#pragma unroll 1
    for (int k0 = 0; k0 < K; k0 += 16) {
        sm.As[ca + 0][ra] = a0.x; sm.As[ca + 1][ra] = a0.y;
        sm.As[ca + 2][ra] = a0.z; sm.As[ca + 3][ra] = a0.w;
        sm.As[ca + 4][ra] = a1.x; sm.As[ca + 5][ra] = a1.y;
        sm.As[ca + 6][ra] = a1.z; sm.As[ca + 7][ra] = a1.w;
        *(float4*)&sm.Bs[rb     ][cb] = b0;
        *(float4*)&sm.Bs[rb +  4][cb] = b1;
        *(float4*)&sm.Bs[rb +  8][cb] = b2;
        *(float4*)&sm.Bs[rb + 12][cb] = b3;
        __syncthreads();

        if (k0 + 16 < K) {
            a0 = *(const float4*)(Ap + k0 + 16);
            a1 = *(const float4*)(Ap + k0 + 20);
            b0 = *(const float4*)(Wp + (size_t)(k0 + 16 + rb     ) * N);
            b1 = *(const float4*)(Wp + (size_t)(k0 + 16 + rb +  4) * N);
            b2 = *(const float4*)(Wp + (size_t)(k0 + 16 + rb +  8) * N);
            b3 = *(const float4*)(Wp + (size_t)(k0 + 16 + rb + 12) * N);
        }
#pragma unroll
        for (int k = 0; k < 16; k++) {
            float4 av0 = *(const float4*)&sm.As[k][ty * 8];
            float4 av1 = *(const float4*)&sm.As[k][ty * 8 + 4];
            const ull* bp = (const ull*)&sm.Bs[k][tx * 8];
            ull bq0 = bp[0], bq1 = bp[1], bq2 = bp[2], bq3 = bp[3];
            float am[8] = {av0.x, av0.y, av0.z, av0.w, av1.x, av1.y, av1.z, av1.w};
#pragma unroll
            for (int i = 0; i < 8; i++) {
                ull ap = pack2(am[i], am[i]);
                fma2(acc[i][0], ap, bq0);
                fma2(acc[i][1], ap, bq1);
                fma2(acc[i][2], ap, bq2);
                fma2(acc[i][3], ap, bq3);
            }
        }
        __syncthreads();
    }

    float4 bb0 = *(const float4*)&bias[n0 + tx * 8];
    float4 bb1 = *(const float4*)&bias[n0 + tx * 8 + 4];
    float bs[8] = {bb0.x, bb0.y, bb0.z, bb0.w, bb1.x, bb1.y, bb1.z, bb1.w};
#pragma unroll
    for (int i = 0; i < 8; i++) {
        int m = m0 + ty * 8 + i;
        float o[8];
#pragma unroll
        for (int p = 0; p < 4; p++) {
            float2 f = unpack2(acc[i][p]);
            o[2 * p] = f.x + bs[2 * p];
            o[2 * p + 1] = f.y + bs[2 * p + 1];
        }
        if (relu) {
#pragma unroll
            for (int j = 0; j < 8; j++) o[j] = fmaxf(o[j], 0.f);
        }
        *(float4*)&C[(size_t)m * N + n0 + tx * 8]     = make_float4(o[0], o[1], o[2], o[3]);
        *(float4*)&C[(size_t)m * N + n0 + tx * 8 + 4] = make_float4(o[4], o[5], o[6], o[7]);
    }
}

// fused QKV + scorer-hidden: 14 n-blocks = Q(4)|K(4)|V(4)|H1(2)
__global__ void __launch_bounds__(128) gemm_qkvh(const float* __restrict__ x,
    const float* __restrict__ Wq, const float* __restrict__ bq,
    const float* __restrict__ Wk, const float* __restrict__ bk,
    const float* __restrict__ Wv, const float* __restrict__ bv,
    const float* __restrict__ Ws1, const float* __restrict__ bs1)
{
    __shared__ GS sm;
    int nb = blockIdx.x;
    int m0 = blockIdx.y * 64;
    if (nb < 4)
        gemm_body(sm, x, Wq, bq, g_Q, 512, 512, 0, m0, nb * 128);
    else if (nb < 8)
        gemm_body(sm, x, Wk, bk, g_K, 512, 512, 0, m0, (nb - 4) * 128);
    else if (nb < 12)
        gemm_body(sm, x, Wv, bv, g_V, 512, 512, 0, m0, (nb - 8) * 128);
    else
        gemm_body(sm, x, Ws1, bs1, g_H1, 256, 512, 1, m0, (nb - 12) * 128);
}

__global__ void __launch_bounds__(128) gemm_out(const float* __restrict__ A,
    const float* __restrict__ W, const float* __restrict__ bias, float* __restrict__ C)
{
    __shared__ GS sm;
    gemm_body(sm, A, W, bias, C, 512, 512, 0, blockIdx.y * 64, blockIdx.x * 128);
}

// ---------------- importance -----------------------------------------------------
__global__ void imp_kernel(const float* __restrict__ H1, const float* __restrict__ Ws2,
                           const float* __restrict__ bs2, float* __restrict__ IMP)
{
    int row = blockIdx.x * 8 + (threadIdx.x >> 5);
    int l   = threadIdx.x & 31;
    const float* h = H1 + (size_t)row * 256;
    float acc = 0.f;
#pragma unroll
    for (int c = l; c < 256; c += 32) acc += h[c] * Ws2[c];
#pragma unroll
    for (int o = 16; o; o >>= 1) acc += __shfl_xor_sync(0xffffffffu, acc, o);
    if (l == 0) {
        float z = acc + bs2[0];
        IMP[row] = 1.f / (1.f + __expf(-z));
    }
}

// ---------------- top-k: rank-count flags (parallel) + scan compaction ------------
__global__ void topk_flag(const float* __restrict__ IMP, int* __restrict__ FLAG)
{
    int b = blockIdx.x, chunk = blockIdx.y;
    __shared__ float s[SS];
    for (int i = threadIdx.x; i < SS; i += 256) s[i] = IMP[b * SS + i];
    __syncthreads();
    int i = chunk * 256 + threadIdx.x;
    float vi = s[i];
    int cnt = 0;
#pragma unroll 8
    for (int j = 0; j < SS; j++) {
        float vj = s[j];
        cnt += (vj > vi) || (vj == vi && j < i);
    }
    FLAG[b * SS + i] = (cnt < KTOP) ? 1 : 0;
}

__global__ void topk_compact(const int* __restrict__ FLAG, int* __restrict__ LIST)
{
    int b = blockIdx.x;
    __shared__ int f[SS];
    __shared__ int cs[256];
    for (int i = threadIdx.x; i < SS; i += 256) f[i] = FLAG[b * SS + i];
    __syncthreads();
    int t = threadIdx.x;
    int sum = 0;
#pragma unroll
    for (int j = 0; j < 8; j++) sum += f[t * 8 + j];
    cs[t] = sum;
    __syncthreads();
    // Hillis-Steele inclusive scan over 256
#pragma unroll
    for (int off = 1; off < 256; off <<= 1) {
        int v = (t >= off) ? cs[t - off] : 0;
        __syncthreads();
        cs[t] += v;
        __syncthreads();
    }
    int pos = cs[t] - sum;   // exclusive prefix
#pragma unroll
    for (int j = 0; j < 8; j++) {
        int i = t * 8 + j;
        if (f[i]) LIST[b * KTOP + pos++] = i;
    }
}

// ---------------- kernel A: non-important rows (<=33 keys) -----------------------
__global__ void attn_sparse(const float* __restrict__ Q, const float* __restrict__ K,
                            const float* __restrict__ V, const int* __restrict__ rand_idx,
                            const int* __restrict__ FLAG, float* __restrict__ ATT)
{
    int bi = blockIdx.x;
    if (FLAG[bi]) return;
    int b = bi >> 11, i = bi & (SS - 1);

    __shared__ float qsh[SD];
    __shared__ int   list[40];
    __shared__ int   nk_sh;
    __shared__ float p[SH][64];

    const float* qrow = Q + (size_t)bi * SD;
    for (int t = threadIdx.x; t < SD; t += 256) qsh[t] = qrow[t];

    if (threadIdx.x == 0) {
        int lo = i - HWIN; if (lo < 0) lo = 0;
        int n = 0;
        for (int j = lo; j <= i; j++) list[n++] = j;
        int nw = n;
        for (int r = 0; r < RC; r++) {
            int j = rand_idx[(size_t)bi * RC + r];
            if (j <= i && j < lo) {
                bool dup = false;
                for (int t = nw; t < n; t++) if (list[t] == j) { dup = true; break; }
                if (!dup) list[n++] = j;
            }
        }
        nk_sh = n;
    }
    __syncthreads();

    int h = threadIdx.x >> 5, l = threadIdx.x & 31;
    int n = nk_sh;
    const ull* qp = (const ull*)(qsh + h * SHD);   // 32 dim-pairs

    float s0 = -CUDART_INF_F, s1 = -CUDART_INF_F;
    if (l < n) {
        const float4* kr = (const float4*)(K + ((size_t)b * SS + list[l]) * SD + h * SHD);
        ull acc = 0ull;
#pragma unroll
        for (int d4 = 0; d4 < 16; d4++) {
            float4 kv = kr[d4];
            fma2(acc, pack2(kv.x, kv.y), qp[2 * d4]);
            fma2(acc, pack2(kv.z, kv.w), qp[2 * d4 + 1]);
        }
        float2 f = unpack2(acc);
        s0 = (f.x + f.y) * 0.125f;
    }
    if (l + 32 < n) {
        const float4* kr = (const float4*)(K + ((size_t)b * SS + list[l + 32]) * SD + h * SHD);
        ull acc = 0ull;
#pragma unroll
        for (int d4 = 0; d4 < 16; d4++) {
            float4 kv = kr[d4];
            fma2(acc, pack2(kv.x, kv.y), qp[2 * d4]);
            fma2(acc, pack2(kv.z, kv.w), qp[2 * d4 + 1]);
        }
        float2 f = unpack2(acc);
        s1 = (f.x + f.y) * 0.125f;
    }
    float mx = fmaxf(s0, s1);
#pragma unroll
    for (int o = 16; o; o >>= 1) mx = fmaxf(mx, __shfl_xor_sync(0xffffffffu, mx, o));
    float e0 = (l < n)      ? __expf(s0 - mx) : 0.f;
    float e1 = (l + 32 < n) ? __expf(s1 - mx) : 0.f;
    float sum = e0 + e1;
#pragma unroll
    for (int o = 16; o; o >>= 1) sum += __shfl_xor_sync(0xffffffffu, sum, o);
    float inv = 1.f / sum;
    p[h][l] = e0;
    p[h][l + 32] = e1;
    __syncwarp();

    ull a0p = 0ull, a1p = 0ull;
    float a0t = 0.f, a1t = 0.f;
    int t = 0;
    for (; t + 1 < n; t += 2) {
        const float* v0 = V + ((size_t)b * SS + list[t])     * SD + h * SHD;
        const float* v1 = V + ((size_t)b * SS + list[t + 1]) * SD + h * SHD;
        ull pp = pack2(p[h][t], p[h][t + 1]);
        fma2(a0p, pp, pack2(v0[l],      v1[l]));
        fma2(a1p, pp, pack2(v0[l + 32], v1[l + 32]));
    }
    if (t < n) {
        const float* v0 = V + ((size_t)b * SS + list[t]) * SD + h * SHD;
        float pj = p[h][t];
        a0t = pj * v0[l];
        a1t = pj * v0[l + 32];
    }
    float2 fa0 = unpack2(a0p), fa1 = unpack2(a1p);
    float* orow = ATT + (size_t)bi * SD + h * SHD;
    orow[l]      = (fa0.x + fa0.y + a0t) * inv;
    orow[l + 32] = (fa1.x + fa1.y + a1t) * inv;
}

// ---------------- kernel B: flash-style q-tiled dense rows -----------------------
__global__ void attn_dense(const float* __restrict__ Q, const float* __restrict__ K,
                           const float* __restrict__ V, const int* __restrict__ LIST,
                           float* __restrict__ ATT)
{
    int qt = blockIdx.x, b = blockIdx.y, h = blockIdx.z;
    __shared__ float2 Qs2[32][32];   // [q][dpair]
    __shared__ float2 Ks2[32][33];   // [dpair][j]
    __shared__ float  Vs[32][64];    // [j][d]
    __shared__ float  Ps[32][34];    // [q][j]
    __shared__ int    qi[32];

    int tid = threadIdx.x, w = tid >> 5, l = tid & 31;
    int base = qt * 32;
    int nq = KTOP - base; if (nq > 32) nq = 32;
    if (tid < 32)
        qi[tid] = (tid < nq) ? LIST[b * KTOP + base + tid] : -1;
    __syncthreads();
    int imax = qi[nq - 1];

    int row = tid >> 3, d0 = (tid & 7) * 8;
    {
        int q = qi[row]; int qs = q < 0 ? 0 : q;
        const float* src = Q + ((size_t)b * SS + qs) * SD + h * SHD + d0;
        float4 a = *(const float4*)src;
        float4 c = *(const float4*)(src + 4);
        int dp = d0 >> 1;
        Qs2[row][dp + 0] = make_float2(a.x, a.y);
        Qs2[row][dp + 1] = make_float2(a.z, a.w);
        Qs2[row][dp + 2] = make_float2(c.x, c.y);
        Qs2[row][dp + 3] = make_float2(c.z, c.w);
    }

    int qg[4];
    float m[4], lsum[4];
    ull a0p[4], a1p[4];
#pragma unroll
    for (int c = 0; c < 4; c++) {
        qg[c] = qi[w * 4 + c];
        m[c] = -CUDART_INF_F; lsum[c] = 0.f; a0p[c] = 0ull; a1p[c] = 0ull;
    }

    for (int j0 = 0; j0 <= imax; j0 += 32) {
        __syncthreads();
        {
            int j = j0 + row;
            const float* kp = K + ((size_t)b * SS + j) * SD + h * SHD + d0;
            float4 ka = *(const float4*)kp;
            float4 kb = *(const float4*)(kp + 4);
            int dp = d0 >> 1;
            Ks2[dp + 0][row] = make_float2(ka.x, ka.y);
            Ks2[dp + 1][row] = make_float2(ka.z, ka.w);
            Ks2[dp + 2][row] = make_float2(kb.x, kb.y);
            Ks2[dp + 3][row] = make_float2(kb.z, kb.w);
            const float* vp = V + ((size_t)b * SS + j) * SD + h * SHD + d0;
            *(float4*)&Vs[row][d0]     = *(const float4*)vp;
            *(float4*)&Vs[row][d0 + 4] = *(const float4*)(vp + 4);
        }
        __syncthreads();

        int jg = j0 + l;
        ull acc2[4] = {0ull, 0ull, 0ull, 0ull};
        const ull* Qu = (const ull*)Qs2;
        const ull* Ku = (const ull*)Ks2;
#pragma unroll
        for (int dp = 0; dp < 32; dp++) {
            ull kp = Ku[dp * 33 + l];
#pragma unroll
            for (int c = 0; c < 4; c++)
                fma2(acc2[c], Qu[(w * 4 + c) * 32 + dp], kp);
        }
#pragma unroll
        for (int c = 0; c < 4; c++) {
            float2 sf = unpack2(acc2[c]);
            bool ok = (jg <= qg[c]);
            float sc = ok ? (sf.x + sf.y) * 0.125f : -CUDART_INF_F;
            float tm = sc;
#pragma unroll
            for (int o = 16; o; o >>= 1) tm = fmaxf(tm, __shfl_xor_sync(0xffffffffu, tm, o));
            float newm = fmaxf(m[c], tm);
            float pv = 0.f;
            if (newm != -CUDART_INF_F) {
                pv = ok ? __expf(sc - newm) : 0.f;
                float ps = pv;
#pragma unroll
                for (int o = 16; o; o >>= 1) ps += __shfl_xor_sync(0xffffffffu, ps, o);
                float scale = (m[c] == -CUDART_INF_F) ? 0.f : __expf(m[c] - newm);
                lsum[c] = lsum[c] * scale + ps;
                ull ss = pack2(scale, scale);
                a0p[c] = mul2(a0p[c], ss);
                a1p[c] = mul2(a1p[c], ss);
                m[c] = newm;
            }
            Ps[w * 4 + c][l] = pv;
        }
        __syncwarp();
#pragma unroll
        for (int jp = 0; jp < 16; jp++) {
            int j = jp * 2;
            ull vpa = pack2(Vs[j][l],      Vs[j + 1][l]);
            ull vpb = pack2(Vs[j][l + 32], Vs[j + 1][l + 32]);
#pragma unroll
            for (int c = 0; c < 4; c++) {
                ull pp = *(const ull*)&Ps[w * 4 + c][j];
                fma2(a0p[c], pp, vpa);
                fma2(a1p[c], pp, vpb);
            }
        }
    }

#pragma unroll
    for (int c = 0; c < 4; c++) {
        if (qg[c] >= 0) {
            float inv = 1.f / lsum[c];
            float2 fa = unpack2(a0p[c]);
            float2 fb = unpack2(a1p[c]);
            float* orow = ATT + ((size_t)b * SS + qg[c]) * SD + h * SHD;
            orow[l]      = (fa.x + fa.y) * inv;
            orow[l + 32] = (fb.x + fb.y) * inv;
        }
    }
}

// ---------------- launch ---------------------------------------------------------
extern "C" void kernel_launch(void* const* d_in, const int* in_sizes, int n_in,
                              void* d_out, int out_size)
{
    const float* x    = (const float*)d_in[0];
    const float* Wq   = (const float*)d_in[1];
    const float* bq   = (const float*)d_in[2];
    const float* Wk   = (const float*)d_in[3];
    const float* bk   = (const float*)d_in[4];
    const float* Wv   = (const float*)d_in[5];
    const float* bv   = (const float*)d_in[6];
    const float* Wo   = (const float*)d_in[7];
    const float* bo   = (const float*)d_in[8];
    const float* Ws1  = (const float*)d_in[9];
    const float* bs1  = (const float*)d_in[10];
    const float* Ws2  = (const float*)d_in[11];
    const float* bs2  = (const float*)d_in[12];
    const int*   ridx = (const int*)  d_in[13];
    float* out = (float*)d_out;

    float *Q, *K, *V, *H1, *IMP, *ATT;
    int *FLAG, *LIST;
    cudaGetSymbolAddress((void**)&Q,   g_Q);
    cudaGetSymbolAddress((void**)&K,   g_K);
    cudaGetSymbolAddress((void**)&V,   g_V);
    cudaGetSymbolAddress((void**)&H1,  g_H1);
    cudaGetSymbolAddress((void**)&IMP, g_IMP);
    cudaGetSymbolAddress((void**)&ATT, g_ATT);
    cudaGetSymbolAddress((void**)&FLAG, g_FLAG);
    cudaGetSymbolAddress((void**)&LIST, g_LIST);

    gemm_qkvh<<<dim3(14, 64), 128>>>(x, Wq, bq, Wk, bk, Wv, bv, Ws1, bs1);

    imp_kernel<<<MROWS / 8, 256>>>(H1, Ws2, bs2, IMP);
    topk_flag<<<dim3(SB, 8), 256>>>(IMP, FLAG);
    topk_compact<<<SB, 256>>>(FLAG, LIST);

    attn_sparse<<<MROWS, 256>>>(Q, K, V, ridx, FLAG, ATT);
    attn_dense<<<dim3(QT, SB, SH), 256>>>(Q, K, V, LIST, ATT);

    gemm_out<<<dim3(4, 64), 128>>>(ATT, Wo, bo, out);
}